// round 1
// baseline (speedup 1.0000x reference)
#include <cuda_runtime.h>
#include <cuda_bf16.h>

// Problem constants (from reference)
#define BB    16     // batch
#define MM    127    // M (= N), ctrl grid is (M+1)x(N+1) = 128x128
#define PP    3      // degree P (= Q)
#define KLEN  132    // M + P + 2
#define NSPAN 126    // KLEN - 2*deg
#define SS    256    // SU = SV
#define CDIM  3
#define EPSF  1e-8f

// Scratch (no allocs allowed -> __device__ globals)
__device__ float g_Nu[BB][4][SS];
__device__ float g_Nv[BB][4][SS];
__device__ int   g_uspan[BB][SS];
__device__ int   g_vspan[BB][SS];

// ---------------------------------------------------------------------------
// Prep: normalize knots (exact serial cumsum), find spans (argmin with
// first-occurrence tie-break, replicating jnp semantics), cubic Cox-de-Boor
// basis replicating the reference's exact FP expression order.
// One block per batch; 256 threads handle the 256 u and 256 v samples.
// ---------------------------------------------------------------------------
__global__ __launch_bounds__(SS) void prep_kernel(
    const float* __restrict__ knot_u,
    const float* __restrict__ knot_v,
    const float* __restrict__ uu,
    const float* __restrict__ vv)
{
    const int b = blockIdx.x;
    __shared__ float sU[KLEN];
    __shared__ float sV[KLEN];

    // Sequential cumsum + normalize (tiny; one lane each in different warps)
    if (threadIdx.x == 0) {
        float acc = 0.f;
        for (int i = 0; i < KLEN; i++) {
            float w = knot_u[b * KLEN + i];
            acc += (w < 0.f) ? 1e-4f : w;
            sU[i] = acc;
        }
        const float k0 = sU[0];
        const float inv = 1.f / (sU[KLEN - 1] - k0);
        for (int i = 0; i < KLEN; i++) sU[i] = (sU[i] - k0) * inv;
    } else if (threadIdx.x == 32) {
        float acc = 0.f;
        for (int i = 0; i < KLEN; i++) {
            float w = knot_v[b * KLEN + i];
            acc += (w < 0.f) ? 1e-4f : w;
            sV[i] = acc;
        }
        const float k0 = sV[0];
        const float inv = 1.f / (sV[KLEN - 1] - k0);
        for (int i = 0; i < KLEN; i++) sV[i] = (sV[i] - k0) * inv;
    }
    __syncthreads();

    const int s = threadIdx.x;

    // ---- U direction ----
    {
        const float t = uu[s];
        float best; int idx = 0;
        {
            float d = t - sU[3];
            best = (d > EPSF) ? d : 1.0f;
        }
        for (int i = 1; i < NSPAN; i++) {
            float d = t - sU[3 + i];
            float m = (d > EPSF) ? d : 1.0f;
            if (m < best) { best = m; idx = i; }   // strict < => first occurrence
        }
        int span = idx + PP;
        span = (span < PP) ? PP : (span > MM ? MM : span);

        float Ni[4];
        Ni[0] = 1.f; Ni[1] = 0.f; Ni[2] = 0.f; Ni[3] = 0.f;
        #pragma unroll
        for (int k = 1; k <= PP; k++) {
            float saved = 0.f;
            #pragma unroll
            for (int r = 0; r < 3; r++) {
                if (r >= k) break;
                const float K1 = sU[span + r + 1];
                const float K2 = sU[span + 1 - k + r];
                const float denom = (K1 - t) + (t - K2);       // exact ref order
                const float temp  = (denom == 0.f) ? 1e-4f : Ni[r] / denom;
                Ni[r] = saved + (K1 - t) * temp;
                saved = (t - K2) * temp;
            }
            Ni[k] = saved;
        }
        #pragma unroll
        for (int k = 0; k < 4; k++) g_Nu[b][k][s] = Ni[k];
        g_uspan[b][s] = span;
    }

    // ---- V direction ----
    {
        const float t = vv[s];
        float best; int idx = 0;
        {
            float d = t - sV[3];
            best = (d > EPSF) ? d : 1.0f;
        }
        for (int i = 1; i < NSPAN; i++) {
            float d = t - sV[3 + i];
            float m = (d > EPSF) ? d : 1.0f;
            if (m < best) { best = m; idx = i; }
        }
        int span = idx + PP;
        span = (span < PP) ? PP : (span > MM ? MM : span);

        float Ni[4];
        Ni[0] = 1.f; Ni[1] = 0.f; Ni[2] = 0.f; Ni[3] = 0.f;
        #pragma unroll
        for (int k = 1; k <= PP; k++) {
            float saved = 0.f;
            #pragma unroll
            for (int r = 0; r < 3; r++) {
                if (r >= k) break;
                const float K1 = sV[span + r + 1];
                const float K2 = sV[span + 1 - k + r];
                const float denom = (K1 - t) + (t - K2);
                const float temp  = (denom == 0.f) ? 1e-4f : Ni[r] / denom;
                Ni[r] = saved + (K1 - t) * temp;
                saved = (t - K2) * temp;
            }
            Ni[k] = saved;
        }
        #pragma unroll
        for (int k = 0; k < 4; k++) g_Nv[b][k][s] = Ni[k];
        g_vspan[b][s] = span;
    }
}

// ---------------------------------------------------------------------------
// Eval: one block per (b, iu). The 4 control rows [uspan-3 .. uspan] are
// contiguous in memory (rows are the second-from-last dim), so the block
// stages 4*128*3 = 1536 floats into smem with fully coalesced loads.
// Each thread then computes one (b, iu, iv) point from smem.
// ---------------------------------------------------------------------------
__global__ __launch_bounds__(SS) void eval_kernel(
    const float* __restrict__ ctrl,
    float* __restrict__ out)
{
    const int bid = blockIdx.x;          // 0 .. B*SU-1
    const int b  = bid >> 8;
    const int iu = bid & 255;
    const int iv = threadIdx.x;

    __shared__ float s_rows[4 * 128 * CDIM];   // 6 KB
    __shared__ float s_nu[4];

    const int us = g_uspan[b][iu];
    // rows us-3..us are contiguous: base element offset
    const float* cb = ctrl + ((size_t)(b * 128 + (us - 3)) * 128) * CDIM;
    #pragma unroll
    for (int i = threadIdx.x; i < 4 * 128 * CDIM; i += SS)
        s_rows[i] = cb[i];
    if (threadIdx.x < 4) s_nu[threadIdx.x] = g_Nu[b][threadIdx.x][iu];
    __syncthreads();

    const int vs = g_vspan[b][iv];
    const float nv0 = g_Nv[b][0][iv];
    const float nv1 = g_Nv[b][1][iv];
    const float nv2 = g_Nv[b][2][iv];
    const float nv3 = g_Nv[b][3][iv];

    float ax = 0.f, ay = 0.f, az = 0.f;
    const int voff = (vs - 3) * CDIM;
    #pragma unroll
    for (int p = 0; p < 4; p++) {
        const float wu = s_nu[p];
        const float* r = &s_rows[p * 128 * CDIM + voff];
        float w;
        w = wu * nv0; ax += w * r[0];  ay += w * r[1];  az += w * r[2];
        w = wu * nv1; ax += w * r[3];  ay += w * r[4];  az += w * r[5];
        w = wu * nv2; ax += w * r[6];  ay += w * r[7];  az += w * r[8];
        w = wu * nv3; ax += w * r[9];  ay += w * r[10]; az += w * r[11];
    }

    const size_t o = ((size_t)bid * SS + iv) * CDIM;
    out[o]     = ax;
    out[o + 1] = ay;
    out[o + 2] = az;
}

// ---------------------------------------------------------------------------
// Inputs (metadata order): ctrl_pts, knot_u, knot_v, u, v. Output: float32.
// ---------------------------------------------------------------------------
extern "C" void kernel_launch(void* const* d_in, const int* in_sizes, int n_in,
                              void* d_out, int out_size)
{
    const float* ctrl   = (const float*)d_in[0];
    const float* knot_u = (const float*)d_in[1];
    const float* knot_v = (const float*)d_in[2];
    const float* uu     = (const float*)d_in[3];
    const float* vv     = (const float*)d_in[4];
    float* out = (float*)d_out;

    prep_kernel<<<BB, SS>>>(knot_u, knot_v, uu, vv);
    eval_kernel<<<BB * SS, SS>>>(ctrl, out);
}

// round 2
// speedup vs baseline: 1.4136x; 1.4136x over previous
#include <cuda_runtime.h>
#include <cuda_bf16.h>

// Problem constants
#define BB    16
#define MM    127
#define PP    3
#define KLEN  132
#define NSPAN 126
#define SS    256
#define CDIM  3
#define EPSF  1e-8f

// Scratch (__device__ globals; no allocs allowed)
__device__ float4 g_Nu4[BB][SS];    // basis packed per (b,iu)
__device__ float4 g_Nv4[BB][SS];    // basis packed per (b,iv)
__device__ int    g_uspan[BB][SS];
__device__ int    g_vspan[BB][SS];

// ---------------------------------------------------------------------------
// Prep: one block per (dir, batch) = 32 blocks, 256 threads.
// Parallel inclusive scan (Hillis-Steele) for the knot cumsum, normalize,
// per-sample span search (first-occurrence argmin semantics) and cubic basis
// with the reference's exact FP expression order.
// ---------------------------------------------------------------------------
__global__ __launch_bounds__(SS) void prep_kernel(
    const float* __restrict__ knot_u,
    const float* __restrict__ knot_v,
    const float* __restrict__ uu,
    const float* __restrict__ vv)
{
    const int b   = blockIdx.x & 15;
    const int dir = blockIdx.x >> 4;          // 0 = u, 1 = v
    const int tid = threadIdx.x;

    __shared__ float sK[KLEN];

    const float* knots = dir ? knot_v : knot_u;
    if (tid < KLEN) {
        float w = knots[b * KLEN + tid];
        sK[tid] = (w < 0.f) ? 1e-4f : w;
    }
    __syncthreads();

    // Hillis-Steele inclusive scan over 132 elements
    #pragma unroll
    for (int off = 1; off < KLEN; off <<= 1) {
        float add = 0.f;
        if (tid < KLEN && tid >= off) add = sK[tid - off];
        __syncthreads();
        if (tid < KLEN) sK[tid] += add;
        __syncthreads();
    }

    // Normalize
    {
        const float k0  = sK[0];
        const float inv = 1.f / (sK[KLEN - 1] - k0);
        float nk = 0.f;
        if (tid < KLEN) nk = (sK[tid] - k0) * inv;
        __syncthreads();
        if (tid < KLEN) sK[tid] = nk;
        __syncthreads();
    }

    // Per-sample span search + basis
    const int s = tid;
    const float t = (dir ? vv : uu)[s];

    float best; int idx = 0;
    {
        float d = t - sK[3];
        best = (d > EPSF) ? d : 1.0f;
    }
    for (int i = 1; i < NSPAN; i++) {
        float d = t - sK[3 + i];
        float m = (d > EPSF) ? d : 1.0f;
        if (m < best) { best = m; idx = i; }    // strict < => first occurrence
    }
    int span = idx + PP;
    span = (span < PP) ? PP : (span > MM ? MM : span);

    float Ni[4];
    Ni[0] = 1.f; Ni[1] = 0.f; Ni[2] = 0.f; Ni[3] = 0.f;
    #pragma unroll
    for (int k = 1; k <= PP; k++) {
        float saved = 0.f;
        #pragma unroll
        for (int r = 0; r < 3; r++) {
            if (r >= k) break;
            const float K1 = sK[span + r + 1];
            const float K2 = sK[span + 1 - k + r];
            const float denom = (K1 - t) + (t - K2);         // exact ref order
            const float temp  = (denom == 0.f) ? 1e-4f : Ni[r] / denom;
            Ni[r] = saved + (K1 - t) * temp;
            saved = (t - K2) * temp;
        }
        Ni[k] = saved;
    }

    const float4 packed = make_float4(Ni[0], Ni[1], Ni[2], Ni[3]);
    if (dir == 0) { g_Nu4[b][s] = packed; g_uspan[b][s] = span; }
    else          { g_Nv4[b][s] = packed; g_vspan[b][s] = span; }
}

// ---------------------------------------------------------------------------
// Eval: one block per (b, iu). Stage 1: 256 threads cooperatively compute the
// u-contracted row T[j][d] = sum_p Nu_p * ctrl[us-3+p][j][d] (384 floats)
// straight from global (coalesced; rows are contiguous). Stage 2: each thread
// evaluates one (iu, iv) point with 12 conflict-free LDS + 12 FMA.
// ---------------------------------------------------------------------------
__global__ __launch_bounds__(SS) void eval_kernel(
    const float* __restrict__ ctrl,
    float* __restrict__ out)
{
    const int bid = blockIdx.x;        // 0 .. B*SU-1
    const int b  = bid >> 8;
    const int iu = bid & 255;
    const int tid = threadIdx.x;

    __shared__ float sT[128 * CDIM];   // 1.5 KB
    __shared__ float4 s_nu;
    __shared__ int    s_us;

    if (tid == 0) {
        s_nu = g_Nu4[b][iu];
        s_us = g_uspan[b][iu];
    }
    __syncthreads();

    const float4 nu = s_nu;
    const float* cb = ctrl + ((size_t)(b * 128 + (s_us - 3)) * 128) * CDIM;

    // u-contraction: 384 outputs, threads 0..255 take e and e+256
    #pragma unroll
    for (int e = tid; e < 128 * CDIM; e += SS) {
        sT[e] = nu.x * cb[e]
              + nu.y * cb[384 + e]
              + nu.z * cb[768 + e]
              + nu.w * cb[1152 + e];
    }
    __syncthreads();

    // v-contraction: one point per thread
    const int iv = tid;
    const float4 nv = g_Nv4[b][iv];                 // single coalesced LDG.128
    const int voff = (g_vspan[b][iv] - 3) * CDIM;
    const float* tr = sT + voff;                    // stride-12B lanes: conflict-free

    const float ax = nv.x * tr[0] + nv.y * tr[3] + nv.z * tr[6] + nv.w * tr[9];
    const float ay = nv.x * tr[1] + nv.y * tr[4] + nv.z * tr[7] + nv.w * tr[10];
    const float az = nv.x * tr[2] + nv.y * tr[5] + nv.z * tr[8] + nv.w * tr[11];

    const size_t o = ((size_t)bid * SS + iv) * CDIM;
    out[o]     = ax;
    out[o + 1] = ay;
    out[o + 2] = az;
}

// ---------------------------------------------------------------------------
// Inputs (metadata order): ctrl_pts, knot_u, knot_v, u, v. Output: float32.
// ---------------------------------------------------------------------------
extern "C" void kernel_launch(void* const* d_in, const int* in_sizes, int n_in,
                              void* d_out, int out_size)
{
    const float* ctrl   = (const float*)d_in[0];
    const float* knot_u = (const float*)d_in[1];
    const float* knot_v = (const float*)d_in[2];
    const float* uu     = (const float*)d_in[3];
    const float* vv     = (const float*)d_in[4];
    float* out = (float*)d_out;

    prep_kernel<<<2 * BB, SS>>>(knot_u, knot_v, uu, vv);
    eval_kernel<<<BB * SS, SS>>>(ctrl, out);
}

// round 3
// speedup vs baseline: 1.8246x; 1.2907x over previous
#include <cuda_runtime.h>
#include <cuda_bf16.h>

// Problem constants
#define BB    16
#define MM    127
#define PP    3
#define KLEN  132
#define NSPAN 126
#define SS    256
#define CDIM  3
#define EPSF  1e-8f

// Scratch (__device__ globals; no allocs allowed)
__device__ float4 g_Nu4[BB][SS];
__device__ float4 g_Nv4[BB][SS];
__device__ int    g_uspan[BB][SS];
__device__ int    g_vspan[BB][SS];

// ---------------------------------------------------------------------------
// Prep: one block per (dir, batch) = 32 blocks, 256 threads.
// Hillis-Steele scan for cumsum; span via binary search (the reference's
// masked-argmin over a strictly increasing knot vector == last index with
// t - K[3+i] > EPS, a monotone predicate; ties impossible since knots are
// strictly increasing and the 1.0 sentinel can't be matched by d<1).
// Basis uses the reference's exact FP expression order.
// ---------------------------------------------------------------------------
__global__ __launch_bounds__(SS) void prep_kernel(
    const float* __restrict__ knot_u,
    const float* __restrict__ knot_v,
    const float* __restrict__ uu,
    const float* __restrict__ vv)
{
    const int b   = blockIdx.x & 15;
    const int dir = blockIdx.x >> 4;          // 0 = u, 1 = v
    const int tid = threadIdx.x;

    __shared__ float sK[KLEN];

    const float* knots = dir ? knot_v : knot_u;
    if (tid < KLEN) {
        float w = knots[b * KLEN + tid];
        sK[tid] = (w < 0.f) ? 1e-4f : w;
    }
    __syncthreads();

    // Hillis-Steele inclusive scan over 132 elements
    #pragma unroll
    for (int off = 1; off < KLEN; off <<= 1) {
        float add = 0.f;
        if (tid < KLEN && tid >= off) add = sK[tid - off];
        __syncthreads();
        if (tid < KLEN) sK[tid] += add;
        __syncthreads();
    }

    // Normalize
    {
        const float k0  = sK[0];
        const float inv = 1.f / (sK[KLEN - 1] - k0);
        float nk = 0.f;
        if (tid < KLEN) nk = (sK[tid] - k0) * inv;
        __syncthreads();
        if (tid < KLEN) sK[tid] = nk;
        __syncthreads();
    }

    const int s = tid;
    const float t = (dir ? vv : uu)[s];

    // Binary search: last i in [0, NSPAN) with (t - sK[3+i]) > EPS; -1 -> 0.
    int lo = -1, hi = NSPAN;
    while (hi - lo > 1) {
        const int mid = (lo + hi) >> 1;
        if (t - sK[3 + mid] > EPSF) lo = mid; else hi = mid;
    }
    int idx = (lo < 0) ? 0 : lo;
    int span = idx + PP;
    span = (span < PP) ? PP : (span > MM ? MM : span);

    float Ni[4];
    Ni[0] = 1.f; Ni[1] = 0.f; Ni[2] = 0.f; Ni[3] = 0.f;
    #pragma unroll
    for (int k = 1; k <= PP; k++) {
        float saved = 0.f;
        #pragma unroll
        for (int r = 0; r < 3; r++) {
            if (r >= k) break;
            const float K1 = sK[span + r + 1];
            const float K2 = sK[span + 1 - k + r];
            const float denom = (K1 - t) + (t - K2);       // exact ref order
            const float temp  = (denom == 0.f) ? 1e-4f : Ni[r] / denom;
            Ni[r] = saved + (K1 - t) * temp;
            saved = (t - K2) * temp;
        }
        Ni[k] = saved;
    }

    const float4 packed = make_float4(Ni[0], Ni[1], Ni[2], Ni[3]);
    if (dir == 0) { g_Nu4[b][s] = packed; g_uspan[b][s] = span; }
    else          { g_Nv4[b][s] = packed; g_vspan[b][s] = span; }
}

// ---------------------------------------------------------------------------
// Eval: one 128-thread block per (b, iu).
// Stage 1: threads 0..95 compute the u-contracted row as 96 float4 outputs,
//          each from 4 independent LDG.128 (deep MLP, few LSU transactions).
// Stage 2: every thread evaluates TWO points (iv = tid, tid+128); its Nv /
//          vspan operands are issued BEFORE the barrier so their latency
//          hides under stage 1.
// ---------------------------------------------------------------------------
#define EVT 128
__global__ __launch_bounds__(EVT) void eval_kernel(
    const float* __restrict__ ctrl,
    float* __restrict__ out)
{
    const int bid = blockIdx.x;        // 0 .. B*SU-1
    const int b  = bid >> 8;
    const int iu = bid & 255;
    const int tid = threadIdx.x;

    __shared__ float4 sT4[96];         // 1.5 KB: u-contracted row (128x3 floats)

    // Uniform broadcast loads
    const float4 nu = g_Nu4[b][iu];
    const int    us = g_uspan[b][iu];

    // Stage-2 operands: issue early (independent of stage 1)
    const int iv0 = tid, iv1 = tid + EVT;
    const float4 nv0 = g_Nv4[b][iv0];
    const float4 nv1 = g_Nv4[b][iv1];
    const int    vs0 = g_vspan[b][iv0];
    const int    vs1 = g_vspan[b][iv1];

    if (tid < 96) {
        const float4* cb4 = (const float4*)(ctrl + (size_t)(b * 128 + (us - 3)) * 384);
        const float4 r0 = cb4[tid];
        const float4 r1 = cb4[tid + 96];
        const float4 r2 = cb4[tid + 192];
        const float4 r3 = cb4[tid + 288];
        float4 acc;
        acc.x = nu.x * r0.x + nu.y * r1.x + nu.z * r2.x + nu.w * r3.x;
        acc.y = nu.x * r0.y + nu.y * r1.y + nu.z * r2.y + nu.w * r3.y;
        acc.z = nu.x * r0.z + nu.y * r1.z + nu.z * r2.z + nu.w * r3.z;
        acc.w = nu.x * r0.w + nu.y * r1.w + nu.z * r2.w + nu.w * r3.w;
        sT4[tid] = acc;
    }
    __syncthreads();

    const float* sT = (const float*)sT4;
    const size_t obase = (size_t)bid * SS;

    {
        const float* tr = sT + (vs0 - 3) * CDIM;
        const float ax = nv0.x * tr[0] + nv0.y * tr[3] + nv0.z * tr[6] + nv0.w * tr[9];
        const float ay = nv0.x * tr[1] + nv0.y * tr[4] + nv0.z * tr[7] + nv0.w * tr[10];
        const float az = nv0.x * tr[2] + nv0.y * tr[5] + nv0.z * tr[8] + nv0.w * tr[11];
        const size_t o = (obase + iv0) * CDIM;
        out[o] = ax; out[o + 1] = ay; out[o + 2] = az;
    }
    {
        const float* tr = sT + (vs1 - 3) * CDIM;
        const float ax = nv1.x * tr[0] + nv1.y * tr[3] + nv1.z * tr[6] + nv1.w * tr[9];
        const float ay = nv1.x * tr[1] + nv1.y * tr[4] + nv1.z * tr[7] + nv1.w * tr[10];
        const float az = nv1.x * tr[2] + nv1.y * tr[5] + nv1.z * tr[8] + nv1.w * tr[11];
        const size_t o = (obase + iv1) * CDIM;
        out[o] = ax; out[o + 1] = ay; out[o + 2] = az;
    }
}

// ---------------------------------------------------------------------------
// Inputs (metadata order): ctrl_pts, knot_u, knot_v, u, v. Output: float32.
// ---------------------------------------------------------------------------
extern "C" void kernel_launch(void* const* d_in, const int* in_sizes, int n_in,
                              void* d_out, int out_size)
{
    const float* ctrl   = (const float*)d_in[0];
    const float* knot_u = (const float*)d_in[1];
    const float* knot_v = (const float*)d_in[2];
    const float* uu     = (const float*)d_in[3];
    const float* vv     = (const float*)d_in[4];
    float* out = (float*)d_out;

    prep_kernel<<<2 * BB, SS>>>(knot_u, knot_v, uu, vv);
    eval_kernel<<<BB * SS, EVT>>>(ctrl, out);
}